// round 6
// baseline (speedup 1.0000x reference)
#include <cuda_runtime.h>

// BoxBlur 13x13 reflect, (8,64,512,512) fp32. Separable, sliding-window.
// = round-3 winner (192us) with exactly ONE change: pass-1 register ring
//   (1 LDG/output) instead of outgoing-row reload (1.75 LDG/output).

#define Wd 512
#define Hd 512
#define TY 16
#define NT 512
#define PW 513            // vs stride (conflict-free row-strided access)
#define OW 516            // os stride (float4-aligned)
#define KHALF 6
#define RAWH (TY + 12)    // 28

#define SMEM_FLOATS (TY * PW + 8 * OW)
#define SMEM_BYTES  (SMEM_FLOATS * 4)       // 49344 B -> 3 CTAs/SM

__device__ __forceinline__ int reflect_i(int i, int n) {
    // jnp.pad 'reflect', pad (6) < n: single fold.
    if (i < 0) i = -i;
    if (i >= n) i = 2 * n - 2 - i;
    return i;
}

__global__ __launch_bounds__(NT, 3)
void boxblur6(const float* __restrict__ in,
              const float* __restrict__ kern,
              float* __restrict__ out) {
    extern __shared__ float sm[];
    float* __restrict__ vs = sm;             // [TY][PW]  vertical 13-sums
    float* __restrict__ os = sm + TY * PW;   // [8][OW]   output staging

    const int ytile = blockIdx.x;
    const int plane = blockIdx.y;
    const int y0 = ytile * TY;
    const float* __restrict__ ip = in  + (size_t)plane * (Hd * Wd);
    float*       __restrict__ op = out + (size_t)plane * (Hd * Wd);
    const int t = threadIdx.x;               // 0..511
    const float k0 = kern[0];                // 1/169

    // ---- Pass 1: vertical running 13-sum, thread t = column t, reg ring ----
    // Step jj reads row y0 + jj - 6; when jj >= 12, window [jj-12..jj] of
    // reads = input rows (j-6..j+6) for output row j = jj - 12.
    {
        float ring[13];
        float s = 0.0f;
        #pragma unroll
        for (int jj = 0; jj < RAWH; jj++) {             // 28 coalesced LDG.32
            const int gy = reflect_i(y0 + jj - KHALF, Hd);
            const float v = ip[gy * Wd + t];
            s += v;
            if (jj >= 12) {
                vs[(jj - 12) * PW + t] = s;
                s -= ring[(jj - 12) % 13];
            }
            ring[jj % 13] = v;
        }
    }
    __syncthreads();

    // ---- Pass 2: horizontal sliding 13-sums, two 8-row halves ----
    const int rl  = t & 7;          // local row within half
    const int seg = t >> 3;         // 0..63, 8-wide x segment
    const int xb  = seg * 8;
    const int g   = t & 127;        // flush: float4 group
    const int r2  = t >> 7;         // flush: row base (0..3)

    #pragma unroll
    for (int h = 0; h < 2; h++) {
        const int row = h * 8 + rl;
        const float* __restrict__ vrow = vs + row * PW;
        float ring[13];
        float s = 0.0f;
        #pragma unroll
        for (int k = 0; k < 13; k++) {
            const float v = vrow[reflect_i(xb - KHALF + k, Wd)];
            ring[k] = v;
            s += v;
        }
        #pragma unroll
        for (int i = 0; i < 8; i++) {
            os[rl * OW + xb + i] = s * k0;
            const float v = vrow[reflect_i(xb + i + KHALF + 1, Wd)];
            s += v - ring[i];
            ring[i] = v;
        }
        __syncthreads();
        // flush half tile: float4 coalesced (LDS.128 + STG.128)
        #pragma unroll
        for (int rr = 0; rr < 2; rr++) {
            const int rowf = r2 + rr * 4;
            const float4 v4 = *(const float4*)&os[rowf * OW + 4 * g];
            *(float4*)&op[(size_t)(y0 + h * 8 + rowf) * Wd + 4 * g] = v4;
        }
        __syncthreads();
    }
}

extern "C" void kernel_launch(void* const* d_in, const int* in_sizes, int n_in,
                              void* d_out, int out_size) {
    const float* input  = (const float*)d_in[0];   // (8,64,512,512) fp32
    const float* kernel = (const float*)d_in[1];   // (1,13,13) fp32 uniform
    float* out = (float*)d_out;

    cudaFuncSetAttribute(boxblur6, cudaFuncAttributeMaxDynamicSharedMemorySize,
                         SMEM_BYTES);

    dim3 grid(Hd / TY, 8 * 64);    // (32 y-tiles, 512 planes)
    boxblur6<<<grid, NT, SMEM_BYTES>>>(input, kernel, out);
}